// round 12
// baseline (speedup 1.0000x reference)
#include <cuda_runtime.h>
#include <cuda_fp16.h>
#include <math.h>
#include <stdint.h>

// ---------------- problem constants ----------------
#define TOK   4096          // B*N tokens
#define DIMM  2048
#define FUSED 18688
#define FFI   8192
#define NSEQ  2048
#define DH    128
#define K2    10240         // FFI + ATTN_INNER for combined output GEMM

// ---------------- scratch (device globals) ----------------
static __device__ float g_proj[(size_t)TOK * FUSED];        // 306 MB
static __device__ __half g_hh[(size_t)TOK * DIMM];          // LN out hi
static __device__ __half g_hl[(size_t)TOK * DIMM];          // LN out lo
static __device__ __half g_wfTh[(size_t)FUSED * DIMM];      // wf^T (fp16)
static __device__ __half g_w2Th[(size_t)DIMM * K2];         // [wfo;wao]^T
static __device__ __half g_a2h[(size_t)TOK * K2];           // [act|attn] hi
static __device__ __half g_a2l[(size_t)TOK * K2];           // [act|attn] lo
static __device__ __half g_qh[(size_t)TOK * DIMM];          // roped Q fp16
static __device__ __half g_kh[(size_t)TOK * DH];            // roped K fp16
static __device__ __half g_vh[(size_t)TOK * DH];            // V fp16
static __device__ float g_cos[NSEQ * 64];
static __device__ float g_sin[NSEQ * 64];

// ---------------- PTX helpers (arch-generic, sm_80-level) ----------------
__device__ __forceinline__ uint32_t s2u(const void* p) {
    uint32_t a;
    asm("{ .reg .u64 t; cvta.to.shared.u64 t, %1; cvt.u32.u64 %0, t; }"
        : "=r"(a) : "l"(p));
    return a;
}
__device__ __forceinline__ void cpa16(uint32_t dst, const void* src) {
    asm volatile("cp.async.cg.shared.global [%0], [%1], 16;" :: "r"(dst), "l"(src));
}
__device__ __forceinline__ void cpa_commit() {
    asm volatile("cp.async.commit_group;");
}
template <int N>
__device__ __forceinline__ void cpa_wait() {
    asm volatile("cp.async.wait_group %0;" :: "n"(N));
}
__device__ __forceinline__ void ldsm4(uint32_t* r, uint32_t addr) {
    asm volatile("ldmatrix.sync.aligned.m8n8.x4.shared.b16 {%0,%1,%2,%3}, [%4];"
                 : "=r"(r[0]), "=r"(r[1]), "=r"(r[2]), "=r"(r[3]) : "r"(addr));
}
__device__ __forceinline__ void ldsm4t(uint32_t* r, uint32_t addr) {
    asm volatile("ldmatrix.sync.aligned.m8n8.x4.trans.shared.b16 {%0,%1,%2,%3}, [%4];"
                 : "=r"(r[0]), "=r"(r[1]), "=r"(r[2]), "=r"(r[3]) : "r"(addr));
}
__device__ __forceinline__ void mma16816(float* c, const uint32_t* a,
                                         const uint32_t* b) {
    asm volatile(
        "mma.sync.aligned.m16n8k16.row.col.f32.f16.f16.f32 "
        "{%0,%1,%2,%3}, {%4,%5,%6,%7}, {%8,%9}, {%0,%1,%2,%3};"
        : "+f"(c[0]), "+f"(c[1]), "+f"(c[2]), "+f"(c[3])
        : "r"(a[0]), "r"(a[1]), "r"(a[2]), "r"(a[3]), "r"(b[0]), "r"(b[1]));
}
__device__ __forceinline__ uint32_t packh2(float a, float b) {
    __half2 h = __floats2half2_rn(a, b);
    return *(uint32_t*)&h;
}

// ---------------- fp16 2-pass GEMM on mma.sync ----------
#define HGE_STAGE 49152
#define HGE_SMEM  (2 * HGE_STAGE)

__device__ __forceinline__ void hge_load_chunk(const __half* Ah, const __half* Al,
                                               const __half* Bh, int bm, int bn,
                                               int K, int chunk, int s, int tid,
                                               uint32_t sb) {
    int kb = chunk << 6;
    uint32_t st = sb + (uint32_t)(s * HGE_STAGE);
    {
        const __half* asrc = (tid < 128) ? Ah : Al;
        int r = tid & 127;
        const char* g = (const char*)(asrc + (size_t)(bm + r) * K + kb);
        uint32_t d0 = st + ((tid >> 7) ? 16384u : 0u) + (uint32_t)(r << 7);
        int x = r & 7;
#pragma unroll
        for (int c = 0; c < 8; c++) cpa16(d0 + (uint32_t)((c ^ x) << 4), g + (c << 4));
    }
    {
        int g0 = tid << 2;
        int r = g0 >> 3, c0 = g0 & 7;
        const char* g = (const char*)(Bh + (size_t)(bn + r) * K + kb) + (c0 << 4);
        uint32_t d0 = st + 32768u + (uint32_t)(r << 7);
        int x = r & 7;
#pragma unroll
        for (int c = 0; c < 4; c++)
            cpa16(d0 + (uint32_t)(((c0 + c) ^ x) << 4), g + (c << 4));
    }
    cpa_commit();
}

__global__ __launch_bounds__(256, 1) void hf_gemm(
    const __half* __restrict__ Ah, const __half* __restrict__ Al,
    const __half* __restrict__ Bh, float* __restrict__ C, int M, int N, int K) {
    extern __shared__ __align__(128) char smem[];
    uint32_t sb = s2u(smem);
    int tid = threadIdx.x, lane = tid & 31, warp = tid >> 5;
    int bm = blockIdx.x << 7, bn = blockIdx.y << 7;
    int wm = (warp >> 2) << 6, wn = (warp & 3) << 5;
    int nk = K >> 6;

    float acc[4][4][4];
#pragma unroll
    for (int mt = 0; mt < 4; mt++)
#pragma unroll
        for (int nt = 0; nt < 4; nt++)
#pragma unroll
            for (int e = 0; e < 4; e++) acc[mt][nt][e] = 0.f;

    hge_load_chunk(Ah, Al, Bh, bm, bn, K, 0, 0, tid, sb);
    hge_load_chunk(Ah, Al, Bh, bm, bn, K, 1, 1, tid, sb);

    uint32_t a_row = (uint32_t)(wm + (lane & 15)) << 7;
    uint32_t b_row = (uint32_t)(wn + (lane & 7) + ((lane >> 4) << 3)) << 7;
    int ga = lane >> 4;
    int gb = (lane >> 3) & 1;
    int lx = lane & 7;

    for (int i = 0; i < nk; i++) {
        int s = i & 1;
        if (i + 1 < nk) cpa_wait<1>(); else cpa_wait<0>();
        __syncthreads();
        uint32_t st = sb + (uint32_t)(s * HGE_STAGE);
        uint32_t Ahb = st, Alb = st + 16384, Bhb = st + 32768;
#pragma unroll
        for (int kk = 0; kk < 4; kk++) {
            uint32_t xga = (uint32_t)((((kk << 1) + ga) ^ lx)) << 4;
            uint32_t xgb = (uint32_t)((((kk << 1) + gb) ^ lx)) << 4;
            uint32_t ahf[4][4], alf[4][4], bhf[2][4];
#pragma unroll
            for (int mt = 0; mt < 4; mt++) {
                ldsm4(ahf[mt], Ahb + a_row + (mt << 11) + xga);
                ldsm4(alf[mt], Alb + a_row + (mt << 11) + xga);
            }
#pragma unroll
            for (int nt = 0; nt < 2; nt++) ldsm4(bhf[nt], Bhb + b_row + (nt << 11) + xgb);
#pragma unroll
            for (int mt = 0; mt < 4; mt++)
#pragma unroll
                for (int nt = 0; nt < 4; nt++) {
                    const uint32_t* bh2 = &bhf[nt >> 1][(nt & 1) << 1];
                    mma16816(acc[mt][nt], ahf[mt], bh2);
                    mma16816(acc[mt][nt], alf[mt], bh2);
                }
        }
        __syncthreads();
        if (i + 2 < nk) hge_load_chunk(Ah, Al, Bh, bm, bn, K, i + 2, s, tid, sb);
    }

    int r0 = bm + wm + (lane >> 2);
    int c0 = bn + wn + ((lane & 3) << 1);
#pragma unroll
    for (int mt = 0; mt < 4; mt++)
#pragma unroll
        for (int nt = 0; nt < 4; nt++) {
            float2 v0 = make_float2(acc[mt][nt][0], acc[mt][nt][1]);
            float2 v1 = make_float2(acc[mt][nt][2], acc[mt][nt][3]);
            *(float2*)&C[(size_t)(r0 + (mt << 4)) * N + c0 + (nt << 3)] = v0;
            *(float2*)&C[(size_t)(r0 + (mt << 4) + 8) * N + c0 + (nt << 3)] = v1;
        }
}

// ---------------- fp16 flash attention on mma.sync (MQA, causal) ------------
// 128 q-rows/CTA, 64-col K/V tiles, 8 warps x 16 rows. Writes a2[:, FFI:].
// LPT: blockIdx.x=0 -> LARGEST qblk so heavy CTAs start in wave 1.
#define FA_SMEM 98304   // Q 32KB + 2 stages x (K 16KB + V 16KB)

__device__ __forceinline__ void fa_ldkv(int bb, int kb, int s, int tid, uint32_t sb) {
    int half = tid >> 7;              // 0 -> K, 1 -> V
    int u = tid & 127;
    int row = u >> 1, gs = (u & 1) << 3;
    const __half* gsrc = half ? g_vh : g_kh;
    const char* src =
        (const char*)(gsrc + ((size_t)(bb * NSEQ) + kb * 64 + row) * DH + (gs << 3));
    uint32_t d0 = sb + 32768u + (uint32_t)(s * 32768) + (half ? 16384u : 0u) +
                  (uint32_t)(row << 8);
    int x = row & 7;
#pragma unroll
    for (int c = 0; c < 8; c++)
        cpa16(d0 + (uint32_t)(((gs + c) ^ x) << 4), src + (c << 4));
    cpa_commit();
}

__global__ __launch_bounds__(256, 1) void fa_kernel() {
    extern __shared__ __align__(128) char smemA[];
    uint32_t sb = s2u(smemA);
    int tid = threadIdx.x, lane = tid & 31, w = tid >> 5;
    int qblk = gridDim.x - 1 - blockIdx.x;   // LPT: heavy tiles first
    int hh = blockIdx.y, bb = blockIdx.z;
    int qr0 = qblk << 7;
    int nkt = (qblk + 1) << 1;
    int wr0 = w << 4;
    const float scale = 0.08838834764831845f;

    // Q load (bundled into first commit group by fa_ldkv below)
    {
        int row = tid >> 1, gs = (tid & 1) << 3;
        const char* src = (const char*)(g_qh + ((size_t)(bb * NSEQ) + qr0 + row) * DIMM +
                                        hh * DH + (gs << 3));
        uint32_t d0 = sb + (uint32_t)(row << 8);
        int x = row & 7;
#pragma unroll
        for (int c = 0; c < 8; c++)
            cpa16(d0 + (uint32_t)(((gs + c) ^ x) << 4), src + (c << 4));
    }
    fa_ldkv(bb, 0, 0, tid, sb);
    fa_ldkv(bb, 1, 1, tid, sb);

    float m0 = -1e30f, m1 = -1e30f, l0 = 0.f, l1 = 0.f;
    float oac[16][4];
#pragma unroll
    for (int j = 0; j < 16; j++)
#pragma unroll
        for (int e = 0; e < 4; e++) oac[j][e] = 0.f;

    for (int kb = 0; kb < nkt; kb++) {
        int s = kb & 1;
        if (kb + 1 < nkt) cpa_wait<1>(); else cpa_wait<0>();
        __syncthreads();
        uint32_t Kb = sb + 32768u + (uint32_t)(s * 32768);
        uint32_t Vb = Kb + 16384u;

        // S = Q K^T
        float sa[8][4];
#pragma unroll
        for (int j = 0; j < 8; j++)
#pragma unroll
            for (int e = 0; e < 4; e++) sa[j][e] = 0.f;
#pragma unroll
        for (int ks = 0; ks < 8; ks++) {
            uint32_t aq[4];
            int ar = wr0 + (lane & 15);
            ldsm4(aq, sb + (uint32_t)(ar << 8) +
                          (uint32_t)((((ks << 1) + (lane >> 4)) ^ (ar & 7)) << 4));
#pragma unroll
            for (int j2 = 0; j2 < 4; j2++) {
                uint32_t bk[4];
                int br = (j2 << 4) + (lane & 7) + ((lane >> 4) << 3);
                ldsm4(bk, Kb + (uint32_t)(br << 8) +
                              (uint32_t)((((ks << 1) + ((lane >> 3) & 1)) ^ (br & 7)) << 4));
                mma16816(sa[2 * j2], aq, bk);
                mma16816(sa[2 * j2 + 1], aq, bk + 2);
            }
        }

        // mask + scale + online softmax
        int rg0 = qr0 + wr0 + (lane >> 2);
        int cb = (kb << 6) + ((lane & 3) << 1);
        bool dm = ((kb << 6) + 63) > (qr0 + wr0);
        float mx0 = -1e30f, mx1 = -1e30f;
#pragma unroll
        for (int j = 0; j < 8; j++) {
            int c = cb + (j << 3);
            float v0 = sa[j][0] * scale, v1 = sa[j][1] * scale;
            float v2 = sa[j][2] * scale, v3 = sa[j][3] * scale;
            if (dm) {
                if (c > rg0) v0 = -1e30f;
                if (c + 1 > rg0) v1 = -1e30f;
                if (c > rg0 + 8) v2 = -1e30f;
                if (c + 1 > rg0 + 8) v3 = -1e30f;
            }
            sa[j][0] = v0; sa[j][1] = v1; sa[j][2] = v2; sa[j][3] = v3;
            mx0 = fmaxf(mx0, fmaxf(v0, v1));
            mx1 = fmaxf(mx1, fmaxf(v2, v3));
        }
        mx0 = fmaxf(mx0, __shfl_xor_sync(0xffffffffu, mx0, 1));
        mx0 = fmaxf(mx0, __shfl_xor_sync(0xffffffffu, mx0, 2));
        mx1 = fmaxf(mx1, __shfl_xor_sync(0xffffffffu, mx1, 1));
        mx1 = fmaxf(mx1, __shfl_xor_sync(0xffffffffu, mx1, 2));
        float mn0 = fmaxf(m0, mx0), mn1 = fmaxf(m1, mx1);
        float al0 = __expf(m0 - mn0), al1 = __expf(m1 - mn1);
        float ls0 = 0.f, ls1 = 0.f;
        uint32_t ph[8][2];
#pragma unroll
        for (int j = 0; j < 8; j++) {
            float p0 = __expf(sa[j][0] - mn0), p1 = __expf(sa[j][1] - mn0);
            float p2 = __expf(sa[j][2] - mn1), p3 = __expf(sa[j][3] - mn1);
            ls0 += p0 + p1; ls1 += p2 + p3;
            ph[j][0] = packh2(p0, p1);
            ph[j][1] = packh2(p2, p3);
        }
        ls0 += __shfl_xor_sync(0xffffffffu, ls0, 1);
        ls0 += __shfl_xor_sync(0xffffffffu, ls0, 2);
        ls1 += __shfl_xor_sync(0xffffffffu, ls1, 1);
        ls1 += __shfl_xor_sync(0xffffffffu, ls1, 2);
        l0 = l0 * al0 + ls0; l1 = l1 * al1 + ls1;
        m0 = mn0; m1 = mn1;
#pragma unroll
        for (int j = 0; j < 16; j++) {
            oac[j][0] *= al0; oac[j][1] *= al0;
            oac[j][2] *= al1; oac[j][3] *= al1;
        }
        // O += P V
#pragma unroll
        for (int t2 = 0; t2 < 4; t2++) {
            uint32_t pa[4] = {ph[2 * t2][0], ph[2 * t2][1],
                              ph[2 * t2 + 1][0], ph[2 * t2 + 1][1]};
#pragma unroll
            for (int d2 = 0; d2 < 8; d2++) {
                uint32_t bv[4];
                int vr = (t2 << 4) + (lane & 15);
                ldsm4t(bv, Vb + (uint32_t)(vr << 8) +
                               (uint32_t)((((d2 << 1) + (lane >> 4)) ^ (vr & 7)) << 4));
                mma16816(oac[2 * d2], pa, bv);
                mma16816(oac[2 * d2 + 1], pa, bv + 2);
            }
        }
        __syncthreads();
        if (kb + 2 < nkt) fa_ldkv(bb, kb + 2, s, tid, sb);
    }

    // epilogue -> a2[:, FFI + hh*128 + ...] fp16 hi/lo
    float inv0 = 1.f / l0, inv1 = 1.f / l1;
    size_t rt0 = (size_t)(bb * NSEQ + qr0 + wr0 + (lane >> 2));
    int colb = FFI + hh * DH + ((lane & 3) << 1);
#pragma unroll
    for (int jt = 0; jt < 16; jt++) {
        int col = colb + (jt << 3);
        float x0 = oac[jt][0] * inv0, x1 = oac[jt][1] * inv0;
        float x2 = oac[jt][2] * inv1, x3 = oac[jt][3] * inv1;
        __half h0 = __float2half_rn(x0), h1 = __float2half_rn(x1);
        __half h2 = __float2half_rn(x2), h3 = __float2half_rn(x3);
        *(__half2*)(g_a2h + rt0 * K2 + col) = __halves2half2(h0, h1);
        *(__half2*)(g_a2h + (rt0 + 8) * K2 + col) = __halves2half2(h2, h3);
        *(__half2*)(g_a2l + rt0 * K2 + col) =
            __floats2half2_rn(x0 - __half2float(h0), x1 - __half2float(h1));
        *(__half2*)(g_a2l + (rt0 + 8) * K2 + col) =
            __floats2half2_rn(x2 - __half2float(h2), x3 - __half2float(h3));
    }
}

// ---------------- transpose + fp32 -> fp16 (weights) ----------------
__global__ __launch_bounds__(256) void transpose_conv(const float* __restrict__ in,
                                                      int R, int C,
                                                      __half* __restrict__ oh,
                                                      int ldo, int coff) {
    __shared__ float tbuf[32][33];
    int bc = blockIdx.x << 5, br = blockIdx.y << 5;
    int tx = threadIdx.x & 31, ty = threadIdx.x >> 5;
#pragma unroll
    for (int i = 0; i < 32; i += 8)
        tbuf[ty + i][tx] = in[(size_t)(br + ty + i) * C + bc + tx];
    __syncthreads();
#pragma unroll
    for (int i = 0; i < 32; i += 8) {
        float v = tbuf[tx][ty + i];
        size_t o = (size_t)(bc + ty + i) * ldo + coff + br + tx;
        oh[o] = __float2half_rn(v);
    }
}

// ---------------- LayerNorm -> fp16 hi/lo ----------------
__global__ __launch_bounds__(256) void ln_kernel(const float* __restrict__ x,
                                                 const float* __restrict__ gamma,
                                                 const float* __restrict__ beta) {
    int row = blockIdx.x;
    int tid = threadIdx.x;
    const float* xr = x + (size_t)row * DIMM;
    float v[8];
    float s = 0.f, s2 = 0.f;
#pragma unroll
    for (int i = 0; i < 8; i++) {
        float tv = xr[tid + i * 256];
        v[i] = tv; s += tv; s2 += tv * tv;
    }
#pragma unroll
    for (int o = 16; o > 0; o >>= 1) {
        s  += __shfl_xor_sync(0xffffffffu, s,  o);
        s2 += __shfl_xor_sync(0xffffffffu, s2, o);
    }
    __shared__ float rs[8], rs2[8];
    int w = tid >> 5, l = tid & 31;
    if (l == 0) { rs[w] = s; rs2[w] = s2; }
    __syncthreads();
    float S = 0.f, S2 = 0.f;
#pragma unroll
    for (int i = 0; i < 8; i++) { S += rs[i]; S2 += rs2[i]; }
    float mean = S * (1.f / DIMM);
    float var  = S2 * (1.f / DIMM) - mean * mean;
    float r = rsqrtf(var + 1e-5f);
    __half* hh = g_hh + (size_t)row * DIMM;
    __half* hl = g_hl + (size_t)row * DIMM;
#pragma unroll
    for (int i = 0; i < 8; i++) {
        int c = tid + i * 256;
        float y = (v[i] - mean) * r * gamma[c] + beta[c];
        __half hi = __float2half_rn(y);
        hh[c] = hi;
        hl[c] = __float2half_rn(y - __half2float(hi));
    }
}

// ---------------- RoPE tables (fp32 to match reference rounding) ------------
__global__ void rope_table_kernel() {
    int idx = blockIdx.x * blockDim.x + threadIdx.x;
    if (idx >= NSEQ * 64) return;
    int n = idx >> 6, i = idx & 63;
    float invf = 1.f / powf(10000.f, (float)i / 64.f);
    float th = (float)n * invf;      // fp32 multiply, like jnp
    g_cos[idx] = cosf(th);
    g_sin[idx] = sinf(th);
}

// ---------------- RoPE apply + V convert -> fp16 q/k/v buffers ----------------
__global__ void rope_kernel() {
    int idx = blockIdx.x * blockDim.x + threadIdx.x;
    if (idx >= TOK * 18 * 64) return;
    int i = idx & 63;
    int t = idx >> 6;
    int head = t % 18;          // 0..15 = q heads, 16 = k, 17 = v (convert only)
    int row = t / 18;
    if (head == 17) {
        size_t base = (size_t)row * FUSED + 2176;
        size_t o = (size_t)row * DH;
        g_vh[o + i] = __float2half_rn(g_proj[base + i]);
        g_vh[o + i + 64] = __float2half_rn(g_proj[base + i + 64]);
        return;
    }
    int pos = row & (NSEQ - 1);
    float c = g_cos[(pos << 6) + i];
    float s = g_sin[(pos << 6) + i];
    size_t base = (size_t)row * FUSED + (head < 16 ? (head << 7) : 2048);
    float v0 = g_proj[base + i];
    float v1 = g_proj[base + i + 64];
    float r0 = v0 * c - v1 * s;
    float r1 = v1 * c + v0 * s;
    if (head < 16) {
        size_t o = (size_t)row * DIMM + (head << 7);
        g_qh[o + i] = __float2half_rn(r0);
        g_qh[o + i + 64] = __float2half_rn(r1);
    } else {
        size_t o = (size_t)row * DH;
        g_kh[o + i] = __float2half_rn(r0);
        g_kh[o + i + 64] = __float2half_rn(r1);
    }
}

// ---------------- SwiGLU -> fp16 hi/lo into a2 ----------------
__global__ __launch_bounds__(256) void swiglu_kernel() {
    int idx = blockIdx.x * blockDim.x + threadIdx.x;
    if (idx >= TOK * (FFI / 4)) return;
    int row = idx / (FFI / 4);
    int c4 = (idx % (FFI / 4)) << 2;
    const float4 xv = *(const float4*)(g_proj + (size_t)row * FUSED + 2304 + c4);
    const float4 gv = *(const float4*)(g_proj + (size_t)row * FUSED + 2304 + FFI + c4);
    float o[4];
    o[0] = xv.x * gv.x / (1.f + __expf(-gv.x));
    o[1] = xv.y * gv.y / (1.f + __expf(-gv.y));
    o[2] = xv.z * gv.z / (1.f + __expf(-gv.z));
    o[3] = xv.w * gv.w / (1.f + __expf(-gv.w));
    size_t ob = (size_t)row * K2 + c4;
#pragma unroll
    for (int e = 0; e < 4; e++) {
        __half hi = __float2half_rn(o[e]);
        g_a2h[ob + e] = hi;
        g_a2l[ob + e] = __float2half_rn(o[e] - __half2float(hi));
    }
}

// ---------------- launch ----------------
extern "C" void kernel_launch(void* const* d_in, const int* in_sizes, int n_in,
                              void* d_out, int out_size) {
    (void)in_sizes; (void)n_in; (void)out_size;
    const float* x     = (const float*)d_in[0];
    const float* gamma = (const float*)d_in[1];
    const float* beta  = (const float*)d_in[2];
    const float* wf    = (const float*)d_in[3];
    const float* wao   = (const float*)d_in[4];
    const float* wfo   = (const float*)d_in[5];
    float* out = (float*)d_out;

    __half *phh, *phl, *pwfTh, *pw2Th, *pa2h, *pa2l;
    float* pproj;
    cudaGetSymbolAddress((void**)&pproj, g_proj);
    cudaGetSymbolAddress((void**)&phh, g_hh);
    cudaGetSymbolAddress((void**)&phl, g_hl);
    cudaGetSymbolAddress((void**)&pwfTh, g_wfTh);
    cudaGetSymbolAddress((void**)&pw2Th, g_w2Th);
    cudaGetSymbolAddress((void**)&pa2h, g_a2h);
    cudaGetSymbolAddress((void**)&pa2l, g_a2l);

    cudaFuncSetAttribute(hf_gemm, cudaFuncAttributeMaxDynamicSharedMemorySize,
                         HGE_SMEM);
    cudaFuncSetAttribute(fa_kernel, cudaFuncAttributeMaxDynamicSharedMemorySize,
                         FA_SMEM);

    // weight conversions (transposed fp16)
    transpose_conv<<<dim3(FUSED / 32, DIMM / 32), 256>>>(wf, DIMM, FUSED,
                                                         pwfTh, DIMM, 0);
    transpose_conv<<<dim3(DIMM / 32, FFI / 32), 256>>>(wfo, FFI, DIMM,
                                                       pw2Th, K2, 0);
    transpose_conv<<<dim3(DIMM / 32, DIMM / 32), 256>>>(wao, DIMM, DIMM,
                                                        pw2Th, K2, FFI);
    // LayerNorm
    ln_kernel<<<TOK, 256>>>(x, gamma, beta);
    // fused projection GEMM: [4096,2048] x [18688,2048]^T -> g_proj
    hf_gemm<<<dim3(TOK / 128, FUSED / 128), 256, HGE_SMEM>>>(
        phh, phl, pwfTh, pproj, TOK, FUSED, DIMM);
    // RoPE + V conversion (fp16 q/k/v buffers)
    rope_table_kernel<<<(NSEQ * 64 + 255) / 256, 256>>>();
    rope_kernel<<<(TOK * 18 * 64 + 255) / 256, 256>>>();
    // flash attention -> a2[:, 8192:]   (LPT-ordered causal tiles)
    fa_kernel<<<dim3(NSEQ / 128, 16, 2), 256, FA_SMEM>>>();
    // swiglu -> a2[:, :8192]
    swiglu_kernel<<<(TOK * (FFI / 4) + 255) / 256, 256>>>();
    // combined output GEMM: [4096,10240] x [2048,10240]^T -> out
    hf_gemm<<<dim3(TOK / 128, DIMM / 128), 256, HGE_SMEM>>>(
        pa2h, pa2l, pw2Th, out, TOK, DIMM, K2);
}

// round 13
// speedup vs baseline: 2.1764x; 2.1764x over previous
#include <cuda_runtime.h>
#include <cuda_fp16.h>
#include <math.h>
#include <stdint.h>

// ---------------- problem constants ----------------
#define TOK   4096          // B*N tokens
#define DIMM  2048
#define FUSED 18688
#define FFI   8192
#define NSEQ  2048
#define DH    128
#define K2    10240         // FFI + ATTN_INNER for combined output GEMM

// ---------------- scratch (device globals) ----------------
static __device__ float g_proj[(size_t)TOK * FUSED];        // 306 MB
static __device__ __half g_hh[(size_t)TOK * DIMM];          // LN out fp16
static __device__ __half g_wfTh[(size_t)FUSED * DIMM];      // wf^T (fp16)
static __device__ __half g_w2Th[(size_t)DIMM * K2];         // [wfo;wao]^T
static __device__ __half g_a2h[(size_t)TOK * K2];           // [act|attn] fp16
static __device__ __half g_qh[(size_t)TOK * DIMM];          // roped Q fp16
static __device__ __half g_kh[(size_t)TOK * DH];            // roped K fp16
static __device__ __half g_vh[(size_t)TOK * DH];            // V fp16
static __device__ float g_cos[NSEQ * 64];
static __device__ float g_sin[NSEQ * 64];

// ---------------- PTX helpers (arch-generic, sm_80-level) ----------------
__device__ __forceinline__ uint32_t s2u(const void* p) {
    uint32_t a;
    asm("{ .reg .u64 t; cvta.to.shared.u64 t, %1; cvt.u32.u64 %0, t; }"
        : "=r"(a) : "l"(p));
    return a;
}
__device__ __forceinline__ void cpa16(uint32_t dst, const void* src) {
    asm volatile("cp.async.cg.shared.global [%0], [%1], 16;" :: "r"(dst), "l"(src));
}
__device__ __forceinline__ void cpa_commit() {
    asm volatile("cp.async.commit_group;");
}
template <int N>
__device__ __forceinline__ void cpa_wait() {
    asm volatile("cp.async.wait_group %0;" :: "n"(N));
}
__device__ __forceinline__ void ldsm4(uint32_t* r, uint32_t addr) {
    asm volatile("ldmatrix.sync.aligned.m8n8.x4.shared.b16 {%0,%1,%2,%3}, [%4];"
                 : "=r"(r[0]), "=r"(r[1]), "=r"(r[2]), "=r"(r[3]) : "r"(addr));
}
__device__ __forceinline__ void ldsm4t(uint32_t* r, uint32_t addr) {
    asm volatile("ldmatrix.sync.aligned.m8n8.x4.trans.shared.b16 {%0,%1,%2,%3}, [%4];"
                 : "=r"(r[0]), "=r"(r[1]), "=r"(r[2]), "=r"(r[3]) : "r"(addr));
}
__device__ __forceinline__ void mma16816(float* c, const uint32_t* a,
                                         const uint32_t* b) {
    asm volatile(
        "mma.sync.aligned.m16n8k16.row.col.f32.f16.f16.f32 "
        "{%0,%1,%2,%3}, {%4,%5,%6,%7}, {%8,%9}, {%0,%1,%2,%3};"
        : "+f"(c[0]), "+f"(c[1]), "+f"(c[2]), "+f"(c[3])
        : "r"(a[0]), "r"(a[1]), "r"(a[2]), "r"(a[3]), "r"(b[0]), "r"(b[1]));
}
__device__ __forceinline__ uint32_t packh2(float a, float b) {
    __half2 h = __floats2half2_rn(a, b);
    return *(uint32_t*)&h;
}

// ---------------- single-pass fp16 GEMM on mma.sync ----------
// C[M,N] = Ah[M,K] * Bh[N,K]^T, fp32 accum.
// 128x128 CTA tile, K-chunk 64, 2-stage cp.async double buffer, ldmatrix feeds.
// smem tile layout: row r (128B) with 16B granule c stored at (c ^ (r&7)).
// Stage = {Ah 16KB, Bh 16KB} = 32KB; 2 stages = 64KB.
#define HGE_STAGE 32768
#define HGE_SMEM  (2 * HGE_STAGE)

__device__ __forceinline__ void hge_load_chunk(const __half* Ah, const __half* Bh,
                                               int bm, int bn, int K, int chunk,
                                               int s, int tid, uint32_t sb) {
    int kb = chunk << 6;
    uint32_t st = sb + (uint32_t)(s * HGE_STAGE);
    // threads 0..127 -> A rows, 128..255 -> B rows; 8 granules (one row) each
    const __half* src = (tid < 128) ? Ah : Bh;
    int rbase = (tid < 128) ? bm : bn;
    int r = tid & 127;
    const char* g = (const char*)(src + (size_t)(rbase + r) * K + kb);
    uint32_t d0 = st + ((tid >> 7) ? 16384u : 0u) + (uint32_t)(r << 7);
    int x = r & 7;
#pragma unroll
    for (int c = 0; c < 8; c++) cpa16(d0 + (uint32_t)((c ^ x) << 4), g + (c << 4));
    cpa_commit();
}

__global__ __launch_bounds__(256, 1) void hf_gemm(
    const __half* __restrict__ Ah, const __half* __restrict__ Bh,
    float* __restrict__ C, int M, int N, int K) {
    extern __shared__ __align__(128) char smem[];
    uint32_t sb = s2u(smem);
    int tid = threadIdx.x, lane = tid & 31, warp = tid >> 5;
    int bm = blockIdx.x << 7, bn = blockIdx.y << 7;   // x = M fast => B-panel L2 reuse
    int wm = (warp >> 2) << 6, wn = (warp & 3) << 5;  // warp tile 64x32
    int nk = K >> 6;

    float acc[4][4][4];
#pragma unroll
    for (int mt = 0; mt < 4; mt++)
#pragma unroll
        for (int nt = 0; nt < 4; nt++)
#pragma unroll
            for (int e = 0; e < 4; e++) acc[mt][nt][e] = 0.f;

    hge_load_chunk(Ah, Bh, bm, bn, K, 0, 0, tid, sb);
    hge_load_chunk(Ah, Bh, bm, bn, K, 1, 1, tid, sb);

    uint32_t a_row = (uint32_t)(wm + (lane & 15)) << 7;
    uint32_t b_row = (uint32_t)(wn + (lane & 7) + ((lane >> 4) << 3)) << 7;
    int ga = lane >> 4;
    int gb = (lane >> 3) & 1;
    int lx = lane & 7;

    for (int i = 0; i < nk; i++) {
        int s = i & 1;
        if (i + 1 < nk) cpa_wait<1>(); else cpa_wait<0>();
        __syncthreads();
        uint32_t st = sb + (uint32_t)(s * HGE_STAGE);
        uint32_t Ahb = st, Bhb = st + 16384;
#pragma unroll
        for (int kk = 0; kk < 4; kk++) {
            uint32_t xga = (uint32_t)((((kk << 1) + ga) ^ lx)) << 4;
            uint32_t xgb = (uint32_t)((((kk << 1) + gb) ^ lx)) << 4;
            uint32_t ahf[4][4], bhf[2][4];
#pragma unroll
            for (int mt = 0; mt < 4; mt++)
                ldsm4(ahf[mt], Ahb + a_row + (mt << 11) + xga);
#pragma unroll
            for (int nt = 0; nt < 2; nt++)
                ldsm4(bhf[nt], Bhb + b_row + (nt << 11) + xgb);
#pragma unroll
            for (int mt = 0; mt < 4; mt++)
#pragma unroll
                for (int nt = 0; nt < 4; nt++)
                    mma16816(acc[mt][nt], ahf[mt], &bhf[nt >> 1][(nt & 1) << 1]);
        }
        __syncthreads();
        if (i + 2 < nk) hge_load_chunk(Ah, Bh, bm, bn, K, i + 2, s, tid, sb);
    }

    int r0 = bm + wm + (lane >> 2);
    int c0 = bn + wn + ((lane & 3) << 1);
#pragma unroll
    for (int mt = 0; mt < 4; mt++)
#pragma unroll
        for (int nt = 0; nt < 4; nt++) {
            float2 v0 = make_float2(acc[mt][nt][0], acc[mt][nt][1]);
            float2 v1 = make_float2(acc[mt][nt][2], acc[mt][nt][3]);
            *(float2*)&C[(size_t)(r0 + (mt << 4)) * N + c0 + (nt << 3)] = v0;
            *(float2*)&C[(size_t)(r0 + (mt << 4) + 8) * N + c0 + (nt << 3)] = v1;
        }
}

// ---------------- fp16 flash attention on mma.sync (MQA, causal) ------------
// 128 q-rows/CTA, 64-col K/V tiles, 8 warps x 16 rows. Writes a2[:, FFI:].
// LPT: blockIdx.x=0 -> LARGEST qblk so heavy CTAs start in wave 1.
#define FA_SMEM 98304   // Q 32KB + 2 stages x (K 16KB + V 16KB)

__device__ __forceinline__ void fa_ldkv(int bb, int kb, int s, int tid, uint32_t sb) {
    int half = tid >> 7;              // 0 -> K, 1 -> V
    int u = tid & 127;
    int row = u >> 1, gs = (u & 1) << 3;
    const __half* gsrc = half ? g_vh : g_kh;
    const char* src =
        (const char*)(gsrc + ((size_t)(bb * NSEQ) + kb * 64 + row) * DH + (gs << 3));
    uint32_t d0 = sb + 32768u + (uint32_t)(s * 32768) + (half ? 16384u : 0u) +
                  (uint32_t)(row << 8);
    int x = row & 7;
#pragma unroll
    for (int c = 0; c < 8; c++)
        cpa16(d0 + (uint32_t)(((gs + c) ^ x) << 4), src + (c << 4));
    cpa_commit();
}

__global__ __launch_bounds__(256, 1) void fa_kernel() {
    extern __shared__ __align__(128) char smemA[];
    uint32_t sb = s2u(smemA);
    int tid = threadIdx.x, lane = tid & 31, w = tid >> 5;
    int qblk = gridDim.x - 1 - blockIdx.x;   // LPT: heavy tiles first
    int hh = blockIdx.y, bb = blockIdx.z;
    int qr0 = qblk << 7;
    int nkt = (qblk + 1) << 1;
    int wr0 = w << 4;
    const float scale = 0.08838834764831845f;

    {   // Q load (bundled into first commit group by fa_ldkv below)
        int row = tid >> 1, gs = (tid & 1) << 3;
        const char* src = (const char*)(g_qh + ((size_t)(bb * NSEQ) + qr0 + row) * DIMM +
                                        hh * DH + (gs << 3));
        uint32_t d0 = sb + (uint32_t)(row << 8);
        int x = row & 7;
#pragma unroll
        for (int c = 0; c < 8; c++)
            cpa16(d0 + (uint32_t)(((gs + c) ^ x) << 4), src + (c << 4));
    }
    fa_ldkv(bb, 0, 0, tid, sb);
    fa_ldkv(bb, 1, 1, tid, sb);

    float m0 = -1e30f, m1 = -1e30f, l0 = 0.f, l1 = 0.f;
    float oac[16][4];
#pragma unroll
    for (int j = 0; j < 16; j++)
#pragma unroll
        for (int e = 0; e < 4; e++) oac[j][e] = 0.f;

    for (int kb = 0; kb < nkt; kb++) {
        int s = kb & 1;
        if (kb + 1 < nkt) cpa_wait<1>(); else cpa_wait<0>();
        __syncthreads();
        uint32_t Kb = sb + 32768u + (uint32_t)(s * 32768);
        uint32_t Vb = Kb + 16384u;

        // S = Q K^T
        float sa[8][4];
#pragma unroll
        for (int j = 0; j < 8; j++)
#pragma unroll
            for (int e = 0; e < 4; e++) sa[j][e] = 0.f;
#pragma unroll
        for (int ks = 0; ks < 8; ks++) {
            uint32_t aq[4];
            int ar = wr0 + (lane & 15);
            ldsm4(aq, sb + (uint32_t)(ar << 8) +
                          (uint32_t)((((ks << 1) + (lane >> 4)) ^ (ar & 7)) << 4));
#pragma unroll
            for (int j2 = 0; j2 < 4; j2++) {
                uint32_t bk[4];
                int br = (j2 << 4) + (lane & 7) + ((lane >> 4) << 3);
                ldsm4(bk, Kb + (uint32_t)(br << 8) +
                              (uint32_t)((((ks << 1) + ((lane >> 3) & 1)) ^ (br & 7)) << 4));
                mma16816(sa[2 * j2], aq, bk);
                mma16816(sa[2 * j2 + 1], aq, bk + 2);
            }
        }

        // mask + scale + online softmax
        int rg0 = qr0 + wr0 + (lane >> 2);
        int cb = (kb << 6) + ((lane & 3) << 1);
        bool dm = ((kb << 6) + 63) > (qr0 + wr0);
        float mx0 = -1e30f, mx1 = -1e30f;
#pragma unroll
        for (int j = 0; j < 8; j++) {
            int c = cb + (j << 3);
            float v0 = sa[j][0] * scale, v1 = sa[j][1] * scale;
            float v2 = sa[j][2] * scale, v3 = sa[j][3] * scale;
            if (dm) {
                if (c > rg0) v0 = -1e30f;
                if (c + 1 > rg0) v1 = -1e30f;
                if (c > rg0 + 8) v2 = -1e30f;
                if (c + 1 > rg0 + 8) v3 = -1e30f;
            }
            sa[j][0] = v0; sa[j][1] = v1; sa[j][2] = v2; sa[j][3] = v3;
            mx0 = fmaxf(mx0, fmaxf(v0, v1));
            mx1 = fmaxf(mx1, fmaxf(v2, v3));
        }
        mx0 = fmaxf(mx0, __shfl_xor_sync(0xffffffffu, mx0, 1));
        mx0 = fmaxf(mx0, __shfl_xor_sync(0xffffffffu, mx0, 2));
        mx1 = fmaxf(mx1, __shfl_xor_sync(0xffffffffu, mx1, 1));
        mx1 = fmaxf(mx1, __shfl_xor_sync(0xffffffffu, mx1, 2));
        float mn0 = fmaxf(m0, mx0), mn1 = fmaxf(m1, mx1);
        float al0 = __expf(m0 - mn0), al1 = __expf(m1 - mn1);
        float ls0 = 0.f, ls1 = 0.f;
        uint32_t ph[8][2];
#pragma unroll
        for (int j = 0; j < 8; j++) {
            float p0 = __expf(sa[j][0] - mn0), p1 = __expf(sa[j][1] - mn0);
            float p2 = __expf(sa[j][2] - mn1), p3 = __expf(sa[j][3] - mn1);
            ls0 += p0 + p1; ls1 += p2 + p3;
            ph[j][0] = packh2(p0, p1);
            ph[j][1] = packh2(p2, p3);
        }
        ls0 += __shfl_xor_sync(0xffffffffu, ls0, 1);
        ls0 += __shfl_xor_sync(0xffffffffu, ls0, 2);
        ls1 += __shfl_xor_sync(0xffffffffu, ls1, 1);
        ls1 += __shfl_xor_sync(0xffffffffu, ls1, 2);
        l0 = l0 * al0 + ls0; l1 = l1 * al1 + ls1;
        m0 = mn0; m1 = mn1;
#pragma unroll
        for (int j = 0; j < 16; j++) {
            oac[j][0] *= al0; oac[j][1] *= al0;
            oac[j][2] *= al1; oac[j][3] *= al1;
        }
        // O += P V
#pragma unroll
        for (int t2 = 0; t2 < 4; t2++) {
            uint32_t pa[4] = {ph[2 * t2][0], ph[2 * t2][1],
                              ph[2 * t2 + 1][0], ph[2 * t2 + 1][1]};
#pragma unroll
            for (int d2 = 0; d2 < 8; d2++) {
                uint32_t bv[4];
                int vr = (t2 << 4) + (lane & 15);
                ldsm4t(bv, Vb + (uint32_t)(vr << 8) +
                               (uint32_t)((((d2 << 1) + (lane >> 4)) ^ (vr & 7)) << 4));
                mma16816(oac[2 * d2], pa, bv);
                mma16816(oac[2 * d2 + 1], pa, bv + 2);
            }
        }
        __syncthreads();
        if (kb + 2 < nkt) fa_ldkv(bb, kb + 2, s, tid, sb);
    }

    // epilogue -> a2[:, FFI + hh*128 + ...] fp16
    float inv0 = 1.f / l0, inv1 = 1.f / l1;
    size_t rt0 = (size_t)(bb * NSEQ + qr0 + wr0 + (lane >> 2));
    int colb = FFI + hh * DH + ((lane & 3) << 1);
#pragma unroll
    for (int jt = 0; jt < 16; jt++) {
        int col = colb + (jt << 3);
        *(__half2*)(g_a2h + rt0 * K2 + col) =
            __floats2half2_rn(oac[jt][0] * inv0, oac[jt][1] * inv0);
        *(__half2*)(g_a2h + (rt0 + 8) * K2 + col) =
            __floats2half2_rn(oac[jt][2] * inv1, oac[jt][3] * inv1);
    }
}

// ---------------- transpose + fp32 -> fp16 (weights) ----------------
__global__ __launch_bounds__(256) void transpose_conv(const float* __restrict__ in,
                                                      int R, int C,
                                                      __half* __restrict__ oh,
                                                      int ldo, int coff) {
    __shared__ float tbuf[32][33];
    int bc = blockIdx.x << 5, br = blockIdx.y << 5;
    int tx = threadIdx.x & 31, ty = threadIdx.x >> 5;
#pragma unroll
    for (int i = 0; i < 32; i += 8)
        tbuf[ty + i][tx] = in[(size_t)(br + ty + i) * C + bc + tx];
    __syncthreads();
#pragma unroll
    for (int i = 0; i < 32; i += 8) {
        float v = tbuf[tx][ty + i];
        size_t o = (size_t)(bc + ty + i) * ldo + coff + br + tx;
        oh[o] = __float2half_rn(v);
    }
}

// ---------------- LayerNorm -> fp16 ----------------
__global__ __launch_bounds__(256) void ln_kernel(const float* __restrict__ x,
                                                 const float* __restrict__ gamma,
                                                 const float* __restrict__ beta) {
    int row = blockIdx.x;
    int tid = threadIdx.x;
    const float* xr = x + (size_t)row * DIMM;
    float v[8];
    float s = 0.f, s2 = 0.f;
#pragma unroll
    for (int i = 0; i < 8; i++) {
        float tv = xr[tid + i * 256];
        v[i] = tv; s += tv; s2 += tv * tv;
    }
#pragma unroll
    for (int o = 16; o > 0; o >>= 1) {
        s  += __shfl_xor_sync(0xffffffffu, s,  o);
        s2 += __shfl_xor_sync(0xffffffffu, s2, o);
    }
    __shared__ float rs[8], rs2[8];
    int w = tid >> 5, l = tid & 31;
    if (l == 0) { rs[w] = s; rs2[w] = s2; }
    __syncthreads();
    float S = 0.f, S2 = 0.f;
#pragma unroll
    for (int i = 0; i < 8; i++) { S += rs[i]; S2 += rs2[i]; }
    float mean = S * (1.f / DIMM);
    float var  = S2 * (1.f / DIMM) - mean * mean;
    float r = rsqrtf(var + 1e-5f);
    __half* hh = g_hh + (size_t)row * DIMM;
#pragma unroll
    for (int i = 0; i < 8; i++) {
        int c = tid + i * 256;
        float y = (v[i] - mean) * r * gamma[c] + beta[c];
        hh[c] = __float2half_rn(y);
    }
}

// ---------------- RoPE tables (fp32 to match reference rounding) ------------
__global__ void rope_table_kernel() {
    int idx = blockIdx.x * blockDim.x + threadIdx.x;
    if (idx >= NSEQ * 64) return;
    int n = idx >> 6, i = idx & 63;
    float invf = 1.f / powf(10000.f, (float)i / 64.f);
    float th = (float)n * invf;      // fp32 multiply, like jnp
    g_cos[idx] = cosf(th);
    g_sin[idx] = sinf(th);
}

// ---------------- RoPE apply + V convert -> fp16 q/k/v buffers --------------
__global__ void rope_kernel() {
    int idx = blockIdx.x * blockDim.x + threadIdx.x;
    if (idx >= TOK * 18 * 64) return;
    int i = idx & 63;
    int t = idx >> 6;
    int head = t % 18;          // 0..15 = q heads, 16 = k, 17 = v (convert only)
    int row = t / 18;
    if (head == 17) {
        size_t base = (size_t)row * FUSED + 2176;
        size_t o = (size_t)row * DH;
        g_vh[o + i] = __float2half_rn(g_proj[base + i]);
        g_vh[o + i + 64] = __float2half_rn(g_proj[base + i + 64]);
        return;
    }
    int pos = row & (NSEQ - 1);
    float c = g_cos[(pos << 6) + i];
    float s = g_sin[(pos << 6) + i];
    size_t base = (size_t)row * FUSED + (head < 16 ? (head << 7) : 2048);
    float v0 = g_proj[base + i];
    float v1 = g_proj[base + i + 64];
    float r0 = v0 * c - v1 * s;
    float r1 = v1 * c + v0 * s;
    if (head < 16) {
        size_t o = (size_t)row * DIMM + (head << 7);
        g_qh[o + i] = __float2half_rn(r0);
        g_qh[o + i + 64] = __float2half_rn(r1);
    } else {
        size_t o = (size_t)row * DH;
        g_kh[o + i] = __float2half_rn(r0);
        g_kh[o + i + 64] = __float2half_rn(r1);
    }
}

// ---------------- SwiGLU -> fp16 into a2 ----------------
__global__ __launch_bounds__(256) void swiglu_kernel() {
    int idx = blockIdx.x * blockDim.x + threadIdx.x;
    if (idx >= TOK * (FFI / 4)) return;
    int row = idx / (FFI / 4);
    int c4 = (idx % (FFI / 4)) << 2;
    const float4 xv = *(const float4*)(g_proj + (size_t)row * FUSED + 2304 + c4);
    const float4 gv = *(const float4*)(g_proj + (size_t)row * FUSED + 2304 + FFI + c4);
    float o0 = xv.x * gv.x / (1.f + __expf(-gv.x));
    float o1 = xv.y * gv.y / (1.f + __expf(-gv.y));
    float o2 = xv.z * gv.z / (1.f + __expf(-gv.z));
    float o3 = xv.w * gv.w / (1.f + __expf(-gv.w));
    __half2* dst = (__half2*)(g_a2h + (size_t)row * K2 + c4);
    dst[0] = __floats2half2_rn(o0, o1);
    dst[1] = __floats2half2_rn(o2, o3);
}

// ---------------- launch ----------------
extern "C" void kernel_launch(void* const* d_in, const int* in_sizes, int n_in,
                              void* d_out, int out_size) {
    (void)in_sizes; (void)n_in; (void)out_size;
    const float* x     = (const float*)d_in[0];
    const float* gamma = (const float*)d_in[1];
    const float* beta  = (const float*)d_in[2];
    const float* wf    = (const float*)d_in[3];
    const float* wao   = (const float*)d_in[4];
    const float* wfo   = (const float*)d_in[5];
    float* out = (float*)d_out;

    __half *phh, *pwfTh, *pw2Th, *pa2h;
    float* pproj;
    cudaGetSymbolAddress((void**)&pproj, g_proj);
    cudaGetSymbolAddress((void**)&phh, g_hh);
    cudaGetSymbolAddress((void**)&pwfTh, g_wfTh);
    cudaGetSymbolAddress((void**)&pw2Th, g_w2Th);
    cudaGetSymbolAddress((void**)&pa2h, g_a2h);

    cudaFuncSetAttribute(hf_gemm, cudaFuncAttributeMaxDynamicSharedMemorySize,
                         HGE_SMEM);
    cudaFuncSetAttribute(fa_kernel, cudaFuncAttributeMaxDynamicSharedMemorySize,
                         FA_SMEM);

    // weight conversions (transposed fp16)
    transpose_conv<<<dim3(FUSED / 32, DIMM / 32), 256>>>(wf, DIMM, FUSED,
                                                         pwfTh, DIMM, 0);
    transpose_conv<<<dim3(DIMM / 32, FFI / 32), 256>>>(wfo, FFI, DIMM,
                                                       pw2Th, K2, 0);
    transpose_conv<<<dim3(DIMM / 32, DIMM / 32), 256>>>(wao, DIMM, DIMM,
                                                        pw2Th, K2, FFI);
    // LayerNorm
    ln_kernel<<<TOK, 256>>>(x, gamma, beta);
    // fused projection GEMM: [4096,2048] x [18688,2048]^T -> g_proj
    hf_gemm<<<dim3(TOK / 128, FUSED / 128), 256, HGE_SMEM>>>(
        phh, pwfTh, pproj, TOK, FUSED, DIMM);
    // RoPE + V conversion (fp16 q/k/v buffers)
    rope_table_kernel<<<(NSEQ * 64 + 255) / 256, 256>>>();
    rope_kernel<<<(TOK * 18 * 64 + 255) / 256, 256>>>();
    // flash attention -> a2[:, 8192:]   (LPT-ordered causal tiles)
    fa_kernel<<<dim3(NSEQ / 128, 16, 2), 256, FA_SMEM>>>();
    // swiglu -> a2[:, :8192]
    swiglu_kernel<<<(TOK * (FFI / 4) + 255) / 256, 256>>>();
    // combined output GEMM: [4096,10240] x [2048,10240]^T -> out
    hf_gemm<<<dim3(TOK / 128, DIMM / 128), 256, HGE_SMEM>>>(
        pa2h, pw2Th, out, TOK, DIMM, K2);
}

// round 14
// speedup vs baseline: 2.1839x; 1.0035x over previous
#include <cuda_runtime.h>
#include <cuda_fp16.h>
#include <math.h>
#include <stdint.h>

// ---------------- problem constants ----------------
#define TOK   4096          // B*N tokens
#define DIMM  2048
#define FUSED 18688
#define FFI   8192
#define NSEQ  2048
#define DH    128
#define K2    10240         // FFI + ATTN_INNER for combined output GEMM

// ---------------- scratch (device globals) ----------------
static __device__ __half g_proj[(size_t)TOK * FUSED];       // 153 MB (fp16 now)
static __device__ __half g_hh[(size_t)TOK * DIMM];          // LN out fp16
static __device__ __half g_wfTh[(size_t)FUSED * DIMM];      // wf^T (fp16)
static __device__ __half g_w2Th[(size_t)DIMM * K2];         // [wfo;wao]^T
static __device__ __half g_a2h[(size_t)TOK * K2];           // [act|attn] fp16
static __device__ __half g_qh[(size_t)TOK * DIMM];          // roped Q fp16
static __device__ __half g_kh[(size_t)TOK * DH];            // roped K fp16
static __device__ __half g_vh[(size_t)TOK * DH];            // V fp16
static __device__ float g_cos[NSEQ * 64];
static __device__ float g_sin[NSEQ * 64];

// ---------------- PTX helpers (arch-generic, sm_80-level) ----------------
__device__ __forceinline__ uint32_t s2u(const void* p) {
    uint32_t a;
    asm("{ .reg .u64 t; cvta.to.shared.u64 t, %1; cvt.u32.u64 %0, t; }"
        : "=r"(a) : "l"(p));
    return a;
}
__device__ __forceinline__ void cpa16(uint32_t dst, const void* src) {
    asm volatile("cp.async.cg.shared.global [%0], [%1], 16;" :: "r"(dst), "l"(src));
}
__device__ __forceinline__ void cpa_commit() {
    asm volatile("cp.async.commit_group;");
}
template <int N>
__device__ __forceinline__ void cpa_wait() {
    asm volatile("cp.async.wait_group %0;" :: "n"(N));
}
__device__ __forceinline__ void ldsm4(uint32_t* r, uint32_t addr) {
    asm volatile("ldmatrix.sync.aligned.m8n8.x4.shared.b16 {%0,%1,%2,%3}, [%4];"
                 : "=r"(r[0]), "=r"(r[1]), "=r"(r[2]), "=r"(r[3]) : "r"(addr));
}
__device__ __forceinline__ void ldsm4t(uint32_t* r, uint32_t addr) {
    asm volatile("ldmatrix.sync.aligned.m8n8.x4.trans.shared.b16 {%0,%1,%2,%3}, [%4];"
                 : "=r"(r[0]), "=r"(r[1]), "=r"(r[2]), "=r"(r[3]) : "r"(addr));
}
__device__ __forceinline__ void mma16816(float* c, const uint32_t* a,
                                         const uint32_t* b) {
    asm volatile(
        "mma.sync.aligned.m16n8k16.row.col.f32.f16.f16.f32 "
        "{%0,%1,%2,%3}, {%4,%5,%6,%7}, {%8,%9}, {%0,%1,%2,%3};"
        : "+f"(c[0]), "+f"(c[1]), "+f"(c[2]), "+f"(c[3])
        : "r"(a[0]), "r"(a[1]), "r"(a[2]), "r"(a[3]), "r"(b[0]), "r"(b[1]));
}
__device__ __forceinline__ uint32_t packh2(float a, float b) {
    __half2 h = __floats2half2_rn(a, b);
    return *(uint32_t*)&h;
}

// ---------------- single-pass fp16 GEMM on mma.sync (output fp16 or fp32) ----
// C[M,N] = Ah[M,K] * Bh[N,K]^T, fp32 accum.
// 128x128 CTA tile, K-chunk 64, 2-stage cp.async double buffer, ldmatrix feeds.
// smem tile layout: row r (128B) with 16B granule c stored at (c ^ (r&7)).
#define HGE_STAGE 32768
#define HGE_SMEM  (2 * HGE_STAGE)

__device__ __forceinline__ void hge_load_chunk(const __half* Ah, const __half* Bh,
                                               int bm, int bn, int K, int chunk,
                                               int s, int tid, uint32_t sb) {
    int kb = chunk << 6;
    uint32_t st = sb + (uint32_t)(s * HGE_STAGE);
    const __half* src = (tid < 128) ? Ah : Bh;
    int rbase = (tid < 128) ? bm : bn;
    int r = tid & 127;
    const char* g = (const char*)(src + (size_t)(rbase + r) * K + kb);
    uint32_t d0 = st + ((tid >> 7) ? 16384u : 0u) + (uint32_t)(r << 7);
    int x = r & 7;
#pragma unroll
    for (int c = 0; c < 8; c++) cpa16(d0 + (uint32_t)((c ^ x) << 4), g + (c << 4));
    cpa_commit();
}

template <typename OT>
__global__ __launch_bounds__(256, 1) void hf_gemm(
    const __half* __restrict__ Ah, const __half* __restrict__ Bh,
    OT* __restrict__ C, int M, int N, int K) {
    extern __shared__ __align__(128) char smem[];
    uint32_t sb = s2u(smem);
    int tid = threadIdx.x, lane = tid & 31, warp = tid >> 5;
    int bm = blockIdx.x << 7, bn = blockIdx.y << 7;   // x = M fast => B-panel L2 reuse
    int wm = (warp >> 2) << 6, wn = (warp & 3) << 5;  // warp tile 64x32
    int nk = K >> 6;

    float acc[4][4][4];
#pragma unroll
    for (int mt = 0; mt < 4; mt++)
#pragma unroll
        for (int nt = 0; nt < 4; nt++)
#pragma unroll
            for (int e = 0; e < 4; e++) acc[mt][nt][e] = 0.f;

    hge_load_chunk(Ah, Bh, bm, bn, K, 0, 0, tid, sb);
    hge_load_chunk(Ah, Bh, bm, bn, K, 1, 1, tid, sb);

    uint32_t a_row = (uint32_t)(wm + (lane & 15)) << 7;
    uint32_t b_row = (uint32_t)(wn + (lane & 7) + ((lane >> 4) << 3)) << 7;
    int ga = lane >> 4;
    int gb = (lane >> 3) & 1;
    int lx = lane & 7;

    for (int i = 0; i < nk; i++) {
        int s = i & 1;
        if (i + 1 < nk) cpa_wait<1>(); else cpa_wait<0>();
        __syncthreads();
        uint32_t st = sb + (uint32_t)(s * HGE_STAGE);
        uint32_t Ahb = st, Bhb = st + 16384;
#pragma unroll
        for (int kk = 0; kk < 4; kk++) {
            uint32_t xga = (uint32_t)((((kk << 1) + ga) ^ lx)) << 4;
            uint32_t xgb = (uint32_t)((((kk << 1) + gb) ^ lx)) << 4;
            uint32_t ahf[4][4], bhf[2][4];
#pragma unroll
            for (int mt = 0; mt < 4; mt++)
                ldsm4(ahf[mt], Ahb + a_row + (mt << 11) + xga);
#pragma unroll
            for (int nt = 0; nt < 2; nt++)
                ldsm4(bhf[nt], Bhb + b_row + (nt << 11) + xgb);
#pragma unroll
            for (int mt = 0; mt < 4; mt++)
#pragma unroll
                for (int nt = 0; nt < 4; nt++)
                    mma16816(acc[mt][nt], ahf[mt], &bhf[nt >> 1][(nt & 1) << 1]);
        }
        __syncthreads();
        if (i + 2 < nk) hge_load_chunk(Ah, Bh, bm, bn, K, i + 2, s, tid, sb);
    }

    int r0 = bm + wm + (lane >> 2);
    int c0 = bn + wn + ((lane & 3) << 1);
#pragma unroll
    for (int mt = 0; mt < 4; mt++)
#pragma unroll
        for (int nt = 0; nt < 4; nt++) {
            if constexpr (sizeof(OT) == 4) {
                float2 v0 = make_float2(acc[mt][nt][0], acc[mt][nt][1]);
                float2 v1 = make_float2(acc[mt][nt][2], acc[mt][nt][3]);
                *(float2*)&C[(size_t)(r0 + (mt << 4)) * N + c0 + (nt << 3)] = v0;
                *(float2*)&C[(size_t)(r0 + (mt << 4) + 8) * N + c0 + (nt << 3)] = v1;
            } else {
                *(__half2*)&C[(size_t)(r0 + (mt << 4)) * N + c0 + (nt << 3)] =
                    __floats2half2_rn(acc[mt][nt][0], acc[mt][nt][1]);
                *(__half2*)&C[(size_t)(r0 + (mt << 4) + 8) * N + c0 + (nt << 3)] =
                    __floats2half2_rn(acc[mt][nt][2], acc[mt][nt][3]);
            }
        }
}

// ---------------- fp16 flash attention on mma.sync (MQA, causal) ------------
// 128 q-rows/CTA, 64-col K/V tiles, 8 warps x 16 rows. Writes a2[:, FFI:].
// LPT: blockIdx.x=0 -> LARGEST qblk so heavy CTAs start in wave 1.
#define FA_SMEM 98304   // Q 32KB + 2 stages x (K 16KB + V 16KB)

__device__ __forceinline__ void fa_ldkv(int bb, int kb, int s, int tid, uint32_t sb) {
    int half = tid >> 7;              // 0 -> K, 1 -> V
    int u = tid & 127;
    int row = u >> 1, gs = (u & 1) << 3;
    const __half* gsrc = half ? g_vh : g_kh;
    const char* src =
        (const char*)(gsrc + ((size_t)(bb * NSEQ) + kb * 64 + row) * DH + (gs << 3));
    uint32_t d0 = sb + 32768u + (uint32_t)(s * 32768) + (half ? 16384u : 0u) +
                  (uint32_t)(row << 8);
    int x = row & 7;
#pragma unroll
    for (int c = 0; c < 8; c++)
        cpa16(d0 + (uint32_t)(((gs + c) ^ x) << 4), src + (c << 4));
    cpa_commit();
}

__global__ __launch_bounds__(256, 1) void fa_kernel() {
    extern __shared__ __align__(128) char smemA[];
    uint32_t sb = s2u(smemA);
    int tid = threadIdx.x, lane = tid & 31, w = tid >> 5;
    int qblk = gridDim.x - 1 - blockIdx.x;   // LPT: heavy tiles first
    int hh = blockIdx.y, bb = blockIdx.z;
    int qr0 = qblk << 7;
    int nkt = (qblk + 1) << 1;
    int wr0 = w << 4;
    const float scale = 0.08838834764831845f;

    {   // Q load (bundled into first commit group by fa_ldkv below)
        int row = tid >> 1, gs = (tid & 1) << 3;
        const char* src = (const char*)(g_qh + ((size_t)(bb * NSEQ) + qr0 + row) * DIMM +
                                        hh * DH + (gs << 3));
        uint32_t d0 = sb + (uint32_t)(row << 8);
        int x = row & 7;
#pragma unroll
        for (int c = 0; c < 8; c++)
            cpa16(d0 + (uint32_t)(((gs + c) ^ x) << 4), src + (c << 4));
    }
    fa_ldkv(bb, 0, 0, tid, sb);
    fa_ldkv(bb, 1, 1, tid, sb);

    float m0 = -1e30f, m1 = -1e30f, l0 = 0.f, l1 = 0.f;
    float oac[16][4];
#pragma unroll
    for (int j = 0; j < 16; j++)
#pragma unroll
        for (int e = 0; e < 4; e++) oac[j][e] = 0.f;

    for (int kb = 0; kb < nkt; kb++) {
        int s = kb & 1;
        if (kb + 1 < nkt) cpa_wait<1>(); else cpa_wait<0>();
        __syncthreads();
        uint32_t Kb = sb + 32768u + (uint32_t)(s * 32768);
        uint32_t Vb = Kb + 16384u;

        // S = Q K^T
        float sa[8][4];
#pragma unroll
        for (int j = 0; j < 8; j++)
#pragma unroll
            for (int e = 0; e < 4; e++) sa[j][e] = 0.f;
#pragma unroll
        for (int ks = 0; ks < 8; ks++) {
            uint32_t aq[4];
            int ar = wr0 + (lane & 15);
            ldsm4(aq, sb + (uint32_t)(ar << 8) +
                          (uint32_t)((((ks << 1) + (lane >> 4)) ^ (ar & 7)) << 4));
#pragma unroll
            for (int j2 = 0; j2 < 4; j2++) {
                uint32_t bk[4];
                int br = (j2 << 4) + (lane & 7) + ((lane >> 4) << 3);
                ldsm4(bk, Kb + (uint32_t)(br << 8) +
                              (uint32_t)((((ks << 1) + ((lane >> 3) & 1)) ^ (br & 7)) << 4));
                mma16816(sa[2 * j2], aq, bk);
                mma16816(sa[2 * j2 + 1], aq, bk + 2);
            }
        }

        // mask + scale + online softmax
        int rg0 = qr0 + wr0 + (lane >> 2);
        int cb = (kb << 6) + ((lane & 3) << 1);
        bool dm = ((kb << 6) + 63) > (qr0 + wr0);
        float mx0 = -1e30f, mx1 = -1e30f;
#pragma unroll
        for (int j = 0; j < 8; j++) {
            int c = cb + (j << 3);
            float v0 = sa[j][0] * scale, v1 = sa[j][1] * scale;
            float v2 = sa[j][2] * scale, v3 = sa[j][3] * scale;
            if (dm) {
                if (c > rg0) v0 = -1e30f;
                if (c + 1 > rg0) v1 = -1e30f;
                if (c > rg0 + 8) v2 = -1e30f;
                if (c + 1 > rg0 + 8) v3 = -1e30f;
            }
            sa[j][0] = v0; sa[j][1] = v1; sa[j][2] = v2; sa[j][3] = v3;
            mx0 = fmaxf(mx0, fmaxf(v0, v1));
            mx1 = fmaxf(mx1, fmaxf(v2, v3));
        }
        mx0 = fmaxf(mx0, __shfl_xor_sync(0xffffffffu, mx0, 1));
        mx0 = fmaxf(mx0, __shfl_xor_sync(0xffffffffu, mx0, 2));
        mx1 = fmaxf(mx1, __shfl_xor_sync(0xffffffffu, mx1, 1));
        mx1 = fmaxf(mx1, __shfl_xor_sync(0xffffffffu, mx1, 2));
        float mn0 = fmaxf(m0, mx0), mn1 = fmaxf(m1, mx1);
        float al0 = __expf(m0 - mn0), al1 = __expf(m1 - mn1);
        float ls0 = 0.f, ls1 = 0.f;
        uint32_t ph[8][2];
#pragma unroll
        for (int j = 0; j < 8; j++) {
            float p0 = __expf(sa[j][0] - mn0), p1 = __expf(sa[j][1] - mn0);
            float p2 = __expf(sa[j][2] - mn1), p3 = __expf(sa[j][3] - mn1);
            ls0 += p0 + p1; ls1 += p2 + p3;
            ph[j][0] = packh2(p0, p1);
            ph[j][1] = packh2(p2, p3);
        }
        ls0 += __shfl_xor_sync(0xffffffffu, ls0, 1);
        ls0 += __shfl_xor_sync(0xffffffffu, ls0, 2);
        ls1 += __shfl_xor_sync(0xffffffffu, ls1, 1);
        ls1 += __shfl_xor_sync(0xffffffffu, ls1, 2);
        l0 = l0 * al0 + ls0; l1 = l1 * al1 + ls1;
        m0 = mn0; m1 = mn1;
#pragma unroll
        for (int j = 0; j < 16; j++) {
            oac[j][0] *= al0; oac[j][1] *= al0;
            oac[j][2] *= al1; oac[j][3] *= al1;
        }
        // O += P V
#pragma unroll
        for (int t2 = 0; t2 < 4; t2++) {
            uint32_t pa[4] = {ph[2 * t2][0], ph[2 * t2][1],
                              ph[2 * t2 + 1][0], ph[2 * t2 + 1][1]};
#pragma unroll
            for (int d2 = 0; d2 < 8; d2++) {
                uint32_t bv[4];
                int vr = (t2 << 4) + (lane & 15);
                ldsm4t(bv, Vb + (uint32_t)(vr << 8) +
                               (uint32_t)((((d2 << 1) + (lane >> 4)) ^ (vr & 7)) << 4));
                mma16816(oac[2 * d2], pa, bv);
                mma16816(oac[2 * d2 + 1], pa, bv + 2);
            }
        }
        __syncthreads();
        if (kb + 2 < nkt) fa_ldkv(bb, kb + 2, s, tid, sb);
    }

    // epilogue -> a2[:, FFI + hh*128 + ...] fp16
    float inv0 = 1.f / l0, inv1 = 1.f / l1;
    size_t rt0 = (size_t)(bb * NSEQ + qr0 + wr0 + (lane >> 2));
    int colb = FFI + hh * DH + ((lane & 3) << 1);
#pragma unroll
    for (int jt = 0; jt < 16; jt++) {
        int col = colb + (jt << 3);
        *(__half2*)(g_a2h + rt0 * K2 + col) =
            __floats2half2_rn(oac[jt][0] * inv0, oac[jt][1] * inv0);
        *(__half2*)(g_a2h + (rt0 + 8) * K2 + col) =
            __floats2half2_rn(oac[jt][2] * inv1, oac[jt][3] * inv1);
    }
}

// ---------------- transpose + fp32 -> fp16 (weights) ----------------
__global__ __launch_bounds__(256) void transpose_conv(const float* __restrict__ in,
                                                      int R, int C,
                                                      __half* __restrict__ oh,
                                                      int ldo, int coff) {
    __shared__ float tbuf[32][33];
    int bc = blockIdx.x << 5, br = blockIdx.y << 5;
    int tx = threadIdx.x & 31, ty = threadIdx.x >> 5;
#pragma unroll
    for (int i = 0; i < 32; i += 8)
        tbuf[ty + i][tx] = in[(size_t)(br + ty + i) * C + bc + tx];
    __syncthreads();
#pragma unroll
    for (int i = 0; i < 32; i += 8) {
        float v = tbuf[tx][ty + i];
        size_t o = (size_t)(bc + ty + i) * ldo + coff + br + tx;
        oh[o] = __float2half_rn(v);
    }
}

// ---------------- LayerNorm -> fp16 ----------------
__global__ __launch_bounds__(256) void ln_kernel(const float* __restrict__ x,
                                                 const float* __restrict__ gamma,
                                                 const float* __restrict__ beta) {
    int row = blockIdx.x;
    int tid = threadIdx.x;
    const float* xr = x + (size_t)row * DIMM;
    float v[8];
    float s = 0.f, s2 = 0.f;
#pragma unroll
    for (int i = 0; i < 8; i++) {
        float tv = xr[tid + i * 256];
        v[i] = tv; s += tv; s2 += tv * tv;
    }
#pragma unroll
    for (int o = 16; o > 0; o >>= 1) {
        s  += __shfl_xor_sync(0xffffffffu, s,  o);
        s2 += __shfl_xor_sync(0xffffffffu, s2, o);
    }
    __shared__ float rs[8], rs2[8];
    int w = tid >> 5, l = tid & 31;
    if (l == 0) { rs[w] = s; rs2[w] = s2; }
    __syncthreads();
    float S = 0.f, S2 = 0.f;
#pragma unroll
    for (int i = 0; i < 8; i++) { S += rs[i]; S2 += rs2[i]; }
    float mean = S * (1.f / DIMM);
    float var  = S2 * (1.f / DIMM) - mean * mean;
    float r = rsqrtf(var + 1e-5f);
    __half* hh = g_hh + (size_t)row * DIMM;
#pragma unroll
    for (int i = 0; i < 8; i++) {
        int c = tid + i * 256;
        float y = (v[i] - mean) * r * gamma[c] + beta[c];
        hh[c] = __float2half_rn(y);
    }
}

// ---------------- RoPE tables (fp32 to match reference rounding) ------------
__global__ void rope_table_kernel() {
    int idx = blockIdx.x * blockDim.x + threadIdx.x;
    if (idx >= NSEQ * 64) return;
    int n = idx >> 6, i = idx & 63;
    float invf = 1.f / powf(10000.f, (float)i / 64.f);
    float th = (float)n * invf;      // fp32 multiply, like jnp
    g_cos[idx] = cosf(th);
    g_sin[idx] = sinf(th);
}

// ---------------- RoPE apply + V copy -> fp16 q/k/v buffers --------------
__global__ void rope_kernel() {
    int idx = blockIdx.x * blockDim.x + threadIdx.x;
    if (idx >= TOK * 18 * 64) return;
    int i = idx & 63;
    int t = idx >> 6;
    int head = t % 18;          // 0..15 = q heads, 16 = k, 17 = v (copy only)
    int row = t / 18;
    if (head == 17) {
        size_t base = (size_t)row * FUSED + 2176;
        size_t o = (size_t)row * DH;
        g_vh[o + i] = g_proj[base + i];
        g_vh[o + i + 64] = g_proj[base + i + 64];
        return;
    }
    int pos = row & (NSEQ - 1);
    float c = g_cos[(pos << 6) + i];
    float s = g_sin[(pos << 6) + i];
    size_t base = (size_t)row * FUSED + (head < 16 ? (head << 7) : 2048);
    float v0 = __half2float(g_proj[base + i]);
    float v1 = __half2float(g_proj[base + i + 64]);
    float r0 = v0 * c - v1 * s;
    float r1 = v1 * c + v0 * s;
    if (head < 16) {
        size_t o = (size_t)row * DIMM + (head << 7);
        g_qh[o + i] = __float2half_rn(r0);
        g_qh[o + i + 64] = __float2half_rn(r1);
    } else {
        size_t o = (size_t)row * DH;
        g_kh[o + i] = __float2half_rn(r0);
        g_kh[o + i + 64] = __float2half_rn(r1);
    }
}

// ---------------- SwiGLU (fp16 in) -> fp16 into a2 ----------------
__global__ __launch_bounds__(256) void swiglu_kernel() {
    int idx = blockIdx.x * blockDim.x + threadIdx.x;
    if (idx >= TOK * (FFI / 4)) return;
    int row = idx / (FFI / 4);
    int c4 = (idx % (FFI / 4)) << 2;
    const __half2* xp = (const __half2*)(g_proj + (size_t)row * FUSED + 2304 + c4);
    const __half2* gp = (const __half2*)(g_proj + (size_t)row * FUSED + 2304 + FFI + c4);
    float2 x01 = __half22float2(xp[0]), x23 = __half22float2(xp[1]);
    float2 g01 = __half22float2(gp[0]), g23 = __half22float2(gp[1]);
    float o0 = x01.x * g01.x / (1.f + __expf(-g01.x));
    float o1 = x01.y * g01.y / (1.f + __expf(-g01.y));
    float o2 = x23.x * g23.x / (1.f + __expf(-g23.x));
    float o3 = x23.y * g23.y / (1.f + __expf(-g23.y));
    __half2* dst = (__half2*)(g_a2h + (size_t)row * K2 + c4);
    dst[0] = __floats2half2_rn(o0, o1);
    dst[1] = __floats2half2_rn(o2, o3);
}

// ---------------- launch ----------------
extern "C" void kernel_launch(void* const* d_in, const int* in_sizes, int n_in,
                              void* d_out, int out_size) {
    (void)in_sizes; (void)n_in; (void)out_size;
    const float* x     = (const float*)d_in[0];
    const float* gamma = (const float*)d_in[1];
    const float* beta  = (const float*)d_in[2];
    const float* wf    = (const float*)d_in[3];
    const float* wao   = (const float*)d_in[4];
    const float* wfo   = (const float*)d_in[5];
    float* out = (float*)d_out;

    __half *phh, *pwfTh, *pw2Th, *pa2h, *pproj;
    cudaGetSymbolAddress((void**)&pproj, g_proj);
    cudaGetSymbolAddress((void**)&phh, g_hh);
    cudaGetSymbolAddress((void**)&pwfTh, g_wfTh);
    cudaGetSymbolAddress((void**)&pw2Th, g_w2Th);
    cudaGetSymbolAddress((void**)&pa2h, g_a2h);

    cudaFuncSetAttribute(hf_gemm<__half>, cudaFuncAttributeMaxDynamicSharedMemorySize,
                         HGE_SMEM);
    cudaFuncSetAttribute(hf_gemm<float>, cudaFuncAttributeMaxDynamicSharedMemorySize,
                         HGE_SMEM);
    cudaFuncSetAttribute(fa_kernel, cudaFuncAttributeMaxDynamicSharedMemorySize,
                         FA_SMEM);

    // weight conversions (transposed fp16)
    transpose_conv<<<dim3(FUSED / 32, DIMM / 32), 256>>>(wf, DIMM, FUSED,
                                                         pwfTh, DIMM, 0);
    transpose_conv<<<dim3(DIMM / 32, FFI / 32), 256>>>(wfo, FFI, DIMM,
                                                       pw2Th, K2, 0);
    transpose_conv<<<dim3(DIMM / 32, DIMM / 32), 256>>>(wao, DIMM, DIMM,
                                                        pw2Th, K2, FFI);
    // LayerNorm
    ln_kernel<<<TOK, 256>>>(x, gamma, beta);
    // fused projection GEMM: [4096,2048] x [18688,2048]^T -> g_proj (fp16)
    hf_gemm<__half><<<dim3(TOK / 128, FUSED / 128), 256, HGE_SMEM>>>(
        phh, pwfTh, pproj, TOK, FUSED, DIMM);
    // RoPE + V copy (fp16 q/k/v buffers)
    rope_table_kernel<<<(NSEQ * 64 + 255) / 256, 256>>>();
    rope_kernel<<<(TOK * 18 * 64 + 255) / 256, 256>>>();
    // flash attention -> a2[:, 8192:]   (LPT-ordered causal tiles)
    fa_kernel<<<dim3(NSEQ / 128, 16, 2), 256, FA_SMEM>>>();
    // swiglu -> a2[:, :8192]
    swiglu_kernel<<<(TOK * (FFI / 4) + 255) / 256, 256>>>();
    // combined output GEMM: [4096,10240] x [2048,10240]^T -> out (fp32)
    hf_gemm<float><<<dim3(TOK / 128, DIMM / 128), 256, HGE_SMEM>>>(
        pa2h, pw2Th, out, TOK, DIMM, K2);
}